// round 1
// baseline (speedup 1.0000x reference)
#include <cuda_runtime.h>
#include <cuda_bf16.h>
#include <math.h>

// ---------------------------------------------------------------------------
// Problem constants
// ---------------------------------------------------------------------------
#define B        8192
#define NF       1725          // 8*106 + 10*60 + 8*33 + 13
#define LDH      1728          // padded leading dim (div by 8 and 4)
#define N1       1024
#define N2       512
#define N3       256
#define NCROSS   4
#define EPS      1e-5f
#define NCHUNK   32            // row chunks for column stats
#define ROWS_PER_CHUNK (B / NCHUNK)

// ---------------------------------------------------------------------------
// Scratch (device globals; no allocation allowed)
// ---------------------------------------------------------------------------
__device__ float g_h   [B * LDH];        // gathered + BN'd features
__device__ float g_w1p [LDH * N1];       // padded W1 (rows 1725..1727 = 0)
__device__ float g_z1  [B * N1];
__device__ float g_z2  [B * N2];
__device__ float g_z3  [B * N3];
__device__ float g_cross_partial[B];     // out_cross . Wout[:1725]
__device__ float g_psum[NCHUNK * LDH];
__device__ float g_psq [NCHUNK * LDH];
__device__ float g_mean[LDH];
__device__ float g_rstd[LDH];

// ---------------------------------------------------------------------------
// 1. Gather embeddings + dense into h (row-major B x LDH, pad cols zeroed)
// ---------------------------------------------------------------------------
__global__ void gather_kernel(const int* __restrict__ sparse,
                              const float* __restrict__ dense,
                              const float* __restrict__ emb_a,
                              const float* __restrict__ emb_b,
                              const float* __restrict__ emb_c)
{
    __shared__ int sp[26];
    const int row = blockIdx.x;
    if (threadIdx.x < 26) sp[threadIdx.x] = sparse[row * 26 + threadIdx.x];
    __syncthreads();

    float* hr = g_h + (size_t)row * LDH;
    for (int j = threadIdx.x; j < LDH; j += blockDim.x) {
        float v;
        if (j < 848) {                       // emb_a: 8 fields x 106
            int f = j / 106, c = j - f * 106;
            int idx = sp[f];
            v = emb_a[((size_t)f * 100000 + idx) * 106 + c];
        } else if (j < 1448) {               // emb_b: 10 fields x 60
            int t = j - 848;
            int f = t / 60, c = t - f * 60;
            int idx = sp[8 + f];
            v = emb_b[((size_t)f * 10000 + idx) * 60 + c];
        } else if (j < 1712) {               // emb_c: 8 fields x 33
            int t = j - 1448;
            int f = t / 33, c = t - f * 33;
            int idx = sp[18 + f];
            v = emb_c[((size_t)f * 1000 + idx) * 33 + c];
        } else if (j < 1725) {               // dense
            v = dense[row * 13 + (j - 1712)];
        } else {
            v = 0.0f;                        // pad
        }
        hr[j] = v;
    }
}

// ---------------------------------------------------------------------------
// 2. Column stats (deterministic two-pass), then normalize (+optional relu)
// ---------------------------------------------------------------------------
__global__ void colstats_partial(const float* __restrict__ X, int ld, int ncols)
{
    int col = blockIdx.x * blockDim.x + threadIdx.x;
    if (col >= ncols) return;
    int r0 = blockIdx.y * ROWS_PER_CHUNK;
    float s = 0.f, q = 0.f;
    const float* p = X + (size_t)r0 * ld + col;
    for (int r = 0; r < ROWS_PER_CHUNK; r++) {
        float v = p[(size_t)r * ld];
        s += v; q += v * v;
    }
    g_psum[blockIdx.y * ncols + col] = s;
    g_psq [blockIdx.y * ncols + col] = q;
}

__global__ void colstats_final(int ncols)
{
    int col = blockIdx.x * blockDim.x + threadIdx.x;
    if (col >= ncols) return;
    float s = 0.f, q = 0.f;
    for (int c = 0; c < NCHUNK; c++) {
        s += g_psum[c * ncols + col];
        q += g_psq [c * ncols + col];
    }
    float mean = s * (1.0f / B);
    float var  = q * (1.0f / B) - mean * mean;
    g_mean[col] = mean;
    g_rstd[col] = rsqrtf(var + EPS);
}

__global__ void bn_apply_v4(float4* __restrict__ X, int ld4, long total4, int relu)
{
    long i = (long)blockIdx.x * blockDim.x + threadIdx.x;
    if (i >= total4) return;
    int c = (int)(i % ld4) * 4;
    float4 v = X[i];
    v.x = (v.x - g_mean[c + 0]) * g_rstd[c + 0];
    v.y = (v.y - g_mean[c + 1]) * g_rstd[c + 1];
    v.z = (v.z - g_mean[c + 2]) * g_rstd[c + 2];
    v.w = (v.w - g_mean[c + 3]) * g_rstd[c + 3];
    if (relu) {
        v.x = fmaxf(v.x, 0.f); v.y = fmaxf(v.y, 0.f);
        v.z = fmaxf(v.z, 0.f); v.w = fmaxf(v.w, 0.f);
    }
    X[i] = v;
}

// ---------------------------------------------------------------------------
// 3. Fused cross network (4 layers) + cross contribution to final logit.
//    One block per row; row lives in SMEM.
// ---------------------------------------------------------------------------
__global__ __launch_bounds__(256)
void cross_kernel(const float* __restrict__ cw,
                  const float* __restrict__ cb,
                  const float* __restrict__ wout)
{
    __shared__ float x0[NF];
    __shared__ float xi[NF];
    __shared__ float red[256];
    const int row = blockIdx.x;
    const int tid = threadIdx.x;

    const float* hr = g_h + (size_t)row * LDH;
    for (int j = tid; j < NF; j += 256) {
        float v = hr[j];
        x0[j] = v; xi[j] = v;
    }
    __syncthreads();

    for (int L = 0; L < NCROSS; L++) {
        const float* w = cw + L * NF;
        float s = 0.f;
        for (int j = tid; j < NF; j += 256) s += xi[j] * w[j];
        red[tid] = s;
        __syncthreads();
        #pragma unroll
        for (int off = 128; off > 0; off >>= 1) {
            if (tid < off) red[tid] += red[tid + off];
            __syncthreads();
        }
        float dot = red[0];
        const float* b = cb + L * NF;
        for (int j = tid; j < NF; j += 256)
            xi[j] = fmaf(x0[j], dot, b[j] + xi[j]);
        __syncthreads();
    }

    float s = 0.f;
    for (int j = tid; j < NF; j += 256) s += xi[j] * wout[j];
    red[tid] = s;
    __syncthreads();
    #pragma unroll
    for (int off = 128; off > 0; off >>= 1) {
        if (tid < off) red[tid] += red[tid + off];
        __syncthreads();
    }
    if (tid == 0) g_cross_partial[row] = red[0];
}

// ---------------------------------------------------------------------------
// 4. SGEMM (fp32): C[MxN] = A[MxK] * Bm[KxN] + bias[N]
//    128x128 block tile, BK=8, 8x8 thread tile, 256 threads.
//    Requires M%128==0, N%128==0, K%8==0, lda/ldb/ldc %4==0.
// ---------------------------------------------------------------------------
__global__ __launch_bounds__(256)
void sgemm_bias(int M, int N, int K,
                const float* __restrict__ A, int lda,
                const float* __restrict__ Bm, int ldb,
                const float* __restrict__ bias,
                float* __restrict__ C, int ldc)
{
    const int BM = 128, BN = 128, BK = 8, TM = 8, TN = 8;
    __shared__ float As[BK][BM];
    __shared__ float Bs[BK][BN];

    const int tid  = threadIdx.x;
    const int tRow = tid / (BN / TN);   // 0..15
    const int tCol = tid % (BN / TN);   // 0..15

    const float* Ab = A + (size_t)blockIdx.y * BM * lda;
    const float* Bb = Bm + (size_t)blockIdx.x * BN;

    const int rowA = tid >> 1;          // 0..127
    const int colA = (tid & 1) * 4;     // 0 or 4
    const int rowB = tid >> 5;          // 0..7
    const int colB = (tid & 31) * 4;    // 0..124

    float acc[TM][TN] = {};
    float regM[TM], regN[TN];

    for (int k0 = 0; k0 < K; k0 += BK) {
        float4 a4 = *(const float4*)(Ab + (size_t)rowA * lda + k0 + colA);
        As[colA + 0][rowA] = a4.x;
        As[colA + 1][rowA] = a4.y;
        As[colA + 2][rowA] = a4.z;
        As[colA + 3][rowA] = a4.w;
        float4 b4 = *(const float4*)(Bb + (size_t)(k0 + rowB) * ldb + colB);
        *(float4*)&Bs[rowB][colB] = b4;
        __syncthreads();

        #pragma unroll
        for (int kk = 0; kk < BK; kk++) {
            #pragma unroll
            for (int i = 0; i < TM; i++) regM[i] = As[kk][tRow * TM + i];
            #pragma unroll
            for (int j = 0; j < TN; j++) regN[j] = Bs[kk][tCol * TN + j];
            #pragma unroll
            for (int i = 0; i < TM; i++)
                #pragma unroll
                for (int j = 0; j < TN; j++)
                    acc[i][j] = fmaf(regM[i], regN[j], acc[i][j]);
        }
        __syncthreads();
    }

    #pragma unroll
    for (int i = 0; i < TM; i++) {
        int m = blockIdx.y * BM + tRow * TM + i;
        #pragma unroll
        for (int j = 0; j < TN; j += 4) {
            int n = blockIdx.x * BN + tCol * TN + j;
            float4 v;
            v.x = acc[i][j + 0] + bias[n + 0];
            v.y = acc[i][j + 1] + bias[n + 1];
            v.z = acc[i][j + 2] + bias[n + 2];
            v.w = acc[i][j + 3] + bias[n + 3];
            *(float4*)(C + (size_t)m * ldc + n) = v;
        }
    }
}

// ---------------------------------------------------------------------------
// 5. Pad W1 (1725 x 1024) into g_w1p (1728 x 1024), zero tail rows
// ---------------------------------------------------------------------------
__global__ void pad_w1(const float* __restrict__ W1)
{
    long i = (long)blockIdx.x * blockDim.x + threadIdx.x;
    long total = (long)LDH * N1;
    if (i >= total) return;
    int k = (int)(i / N1);
    g_w1p[i] = (k < NF) ? W1[i] : 0.0f;
}

// ---------------------------------------------------------------------------
// 6. Final: logits = cross_partial + a3 . Wout[1725:1981]; sigmoid
//    warp per row
// ---------------------------------------------------------------------------
__global__ void final_kernel(const float* __restrict__ wout_tail,
                             float* __restrict__ out)
{
    int row  = blockIdx.x * 8 + (threadIdx.x >> 5);
    int lane = threadIdx.x & 31;
    const float* r = g_z3 + (size_t)row * N3;
    float s = 0.f;
    #pragma unroll
    for (int j = lane; j < N3; j += 32) s += r[j] * wout_tail[j];
    #pragma unroll
    for (int off = 16; off > 0; off >>= 1)
        s += __shfl_down_sync(0xffffffffu, s, off);
    if (lane == 0) {
        float z = s + g_cross_partial[row];
        out[row] = 1.0f / (1.0f + expf(-z));
    }
}

// ---------------------------------------------------------------------------
// Launcher
// ---------------------------------------------------------------------------
extern "C" void kernel_launch(void* const* d_in, const int* in_sizes, int n_in,
                              void* d_out, int out_size)
{
    const int*   sparse  = (const int*)  d_in[0];
    const float* dense   = (const float*)d_in[1];
    const float* emb_a   = (const float*)d_in[2];
    const float* emb_b   = (const float*)d_in[3];
    const float* emb_c   = (const float*)d_in[4];
    const float* cross_w = (const float*)d_in[5];
    const float* cross_b = (const float*)d_in[6];
    const float* W1      = (const float*)d_in[7];
    const float* b1      = (const float*)d_in[8];
    const float* W2      = (const float*)d_in[9];
    const float* b2      = (const float*)d_in[10];
    const float* W3      = (const float*)d_in[11];
    const float* b3      = (const float*)d_in[12];
    const float* Wout    = (const float*)d_in[13];
    float* out = (float*)d_out;

    float *ph, *pw1p, *pz1, *pz2, *pz3;
    cudaGetSymbolAddress((void**)&ph,   g_h);
    cudaGetSymbolAddress((void**)&pw1p, g_w1p);
    cudaGetSymbolAddress((void**)&pz1,  g_z1);
    cudaGetSymbolAddress((void**)&pz2,  g_z2);
    cudaGetSymbolAddress((void**)&pz3,  g_z3);

    // ---- pad W1 ----
    {
        long total = (long)LDH * N1;
        pad_w1<<<(int)((total + 255) / 256), 256>>>(W1);
    }

    // ---- gather ----
    gather_kernel<<<B, 256>>>(sparse, dense, emb_a, emb_b, emb_c);

    // ---- BN(h) ----
    {
        dim3 g((LDH + 127) / 128, NCHUNK);
        colstats_partial<<<g, 128>>>(ph, LDH, LDH);
        colstats_final<<<(LDH + 127) / 128, 128>>>(LDH);
        long t4 = (long)B * (LDH / 4);
        bn_apply_v4<<<(int)((t4 + 255) / 256), 256>>>((float4*)ph, LDH / 4, t4, 0);
    }

    // ---- cross network (fused with Wout head) ----
    cross_kernel<<<B, 256>>>(cross_w, cross_b, Wout);

    // ---- layer 1: z1 = h @ W1p + b1; BN; relu ----
    {
        dim3 grid(N1 / 128, B / 128);
        sgemm_bias<<<grid, 256>>>(B, N1, LDH, ph, LDH, pw1p, N1, b1, pz1, N1);
        dim3 g((N1 + 127) / 128, NCHUNK);
        colstats_partial<<<g, 128>>>(pz1, N1, N1);
        colstats_final<<<(N1 + 127) / 128, 128>>>(N1);
        long t4 = (long)B * (N1 / 4);
        bn_apply_v4<<<(int)((t4 + 255) / 256), 256>>>((float4*)pz1, N1 / 4, t4, 1);
    }

    // ---- layer 2 ----
    {
        dim3 grid(N2 / 128, B / 128);
        sgemm_bias<<<grid, 256>>>(B, N2, N1, pz1, N1, W2, N2, b2, pz2, N2);
        dim3 g((N2 + 127) / 128, NCHUNK);
        colstats_partial<<<g, 128>>>(pz2, N2, N2);
        colstats_final<<<(N2 + 127) / 128, 128>>>(N2);
        long t4 = (long)B * (N2 / 4);
        bn_apply_v4<<<(int)((t4 + 255) / 256), 256>>>((float4*)pz2, N2 / 4, t4, 1);
    }

    // ---- layer 3 ----
    {
        dim3 grid(N3 / 128, B / 128);
        sgemm_bias<<<grid, 256>>>(B, N3, N2, pz2, N2, W3, N3, b3, pz3, N3);
        dim3 g((N3 + 127) / 128, NCHUNK);
        colstats_partial<<<g, 128>>>(pz3, N3, N3);
        colstats_final<<<(N3 + 127) / 128, 128>>>(N3);
        long t4 = (long)B * (N3 / 4);
        bn_apply_v4<<<(int)((t4 + 255) / 256), 256>>>((float4*)pz3, N3 / 4, t4, 1);
    }

    // ---- final head ----
    final_kernel<<<B / 8, 256>>>(Wout + NF, out);
}

// round 3
// speedup vs baseline: 1.1004x; 1.1004x over previous
#include <cuda_runtime.h>
#include <cuda_bf16.h>
#include <math.h>
#include <stdint.h>

// ---------------------------------------------------------------------------
// Problem constants
// ---------------------------------------------------------------------------
#define B        8192
#define NF       1725          // 8*106 + 10*60 + 8*33 + 13
#define LDH      1728          // padded leading dim (div by 16)
#define N1       1024
#define N2       512
#define N3       256
#define NCROSS   4
#define EPS      1e-5f
#define NCHUNK   32            // row chunks for column stats
#define ROWS_PER_CHUNK (B / NCHUNK)

// ---------------------------------------------------------------------------
// Scratch (device globals; no allocation allowed)
// ---------------------------------------------------------------------------
__device__ float g_h   [B * LDH];        // gathered + BN'd features
__device__ float g_w1p [LDH * N1];       // padded W1 (rows 1725..1727 = 0)
__device__ float g_z1  [B * N1];
__device__ float g_z2  [B * N2];
__device__ float g_z3  [B * N3];
__device__ float g_cross_partial[B];     // out_cross . Wout[:1725]
__device__ float g_psum[NCHUNK * LDH];
__device__ float g_psq [NCHUNK * LDH];
__device__ float g_mean[LDH];
__device__ float g_rstd[LDH];

// ---------------------------------------------------------------------------
// 1. Gather embeddings + dense into h (row-major B x LDH, pad cols zeroed)
// ---------------------------------------------------------------------------
__global__ void gather_kernel(const int* __restrict__ sparse,
                              const float* __restrict__ dense,
                              const float* __restrict__ emb_a,
                              const float* __restrict__ emb_b,
                              const float* __restrict__ emb_c)
{
    __shared__ int sp[26];
    const int row = blockIdx.x;
    if (threadIdx.x < 26) sp[threadIdx.x] = sparse[row * 26 + threadIdx.x];
    __syncthreads();

    float* hr = g_h + (size_t)row * LDH;
    for (int j = threadIdx.x; j < LDH; j += blockDim.x) {
        float v;
        if (j < 848) {                       // emb_a: 8 fields x 106
            int f = j / 106, c = j - f * 106;
            int idx = sp[f];
            v = emb_a[((size_t)f * 100000 + idx) * 106 + c];
        } else if (j < 1448) {               // emb_b: 10 fields x 60
            int t = j - 848;
            int f = t / 60, c = t - f * 60;
            int idx = sp[8 + f];
            v = emb_b[((size_t)f * 10000 + idx) * 60 + c];
        } else if (j < 1712) {               // emb_c: 8 fields x 33
            int t = j - 1448;
            int f = t / 33, c = t - f * 33;
            int idx = sp[18 + f];
            v = emb_c[((size_t)f * 1000 + idx) * 33 + c];
        } else if (j < 1725) {               // dense
            v = dense[row * 13 + (j - 1712)];
        } else {
            v = 0.0f;                        // pad
        }
        hr[j] = v;
    }
}

// ---------------------------------------------------------------------------
// 2. Column stats (deterministic two-pass), then normalize (+optional relu)
// ---------------------------------------------------------------------------
__global__ void colstats_partial(const float* __restrict__ X, int ld, int ncols)
{
    int col = blockIdx.x * blockDim.x + threadIdx.x;
    if (col >= ncols) return;
    int r0 = blockIdx.y * ROWS_PER_CHUNK;
    float s = 0.f, q = 0.f;
    const float* p = X + (size_t)r0 * ld + col;
    for (int r = 0; r < ROWS_PER_CHUNK; r++) {
        float v = p[(size_t)r * ld];
        s += v; q += v * v;
    }
    g_psum[blockIdx.y * ncols + col] = s;
    g_psq [blockIdx.y * ncols + col] = q;
}

__global__ void colstats_final(int ncols)
{
    int col = blockIdx.x * blockDim.x + threadIdx.x;
    if (col >= ncols) return;
    float s = 0.f, q = 0.f;
    for (int c = 0; c < NCHUNK; c++) {
        s += g_psum[c * ncols + col];
        q += g_psq [c * ncols + col];
    }
    float mean = s * (1.0f / B);
    float var  = q * (1.0f / B) - mean * mean;
    g_mean[col] = mean;
    g_rstd[col] = rsqrtf(var + EPS);
}

__global__ void bn_apply_v4(float4* __restrict__ X, int ld4, long total4, int relu)
{
    long i = (long)blockIdx.x * blockDim.x + threadIdx.x;
    if (i >= total4) return;
    int c = (int)(i % ld4) * 4;
    float4 v = X[i];
    v.x = (v.x - g_mean[c + 0]) * g_rstd[c + 0];
    v.y = (v.y - g_mean[c + 1]) * g_rstd[c + 1];
    v.z = (v.z - g_mean[c + 2]) * g_rstd[c + 2];
    v.w = (v.w - g_mean[c + 3]) * g_rstd[c + 3];
    if (relu) {
        v.x = fmaxf(v.x, 0.f); v.y = fmaxf(v.y, 0.f);
        v.z = fmaxf(v.z, 0.f); v.w = fmaxf(v.w, 0.f);
    }
    X[i] = v;
}

// ---------------------------------------------------------------------------
// 3. Fused cross network (4 layers) + cross contribution to final logit.
// ---------------------------------------------------------------------------
__global__ __launch_bounds__(256)
void cross_kernel(const float* __restrict__ cw,
                  const float* __restrict__ cb,
                  const float* __restrict__ wout)
{
    __shared__ float x0[NF];
    __shared__ float xi[NF];
    __shared__ float red[256];
    const int row = blockIdx.x;
    const int tid = threadIdx.x;

    const float* hr = g_h + (size_t)row * LDH;
    for (int j = tid; j < NF; j += 256) {
        float v = hr[j];
        x0[j] = v; xi[j] = v;
    }
    __syncthreads();

    for (int L = 0; L < NCROSS; L++) {
        const float* w = cw + L * NF;
        float s = 0.f;
        for (int j = tid; j < NF; j += 256) s += xi[j] * w[j];
        red[tid] = s;
        __syncthreads();
        #pragma unroll
        for (int off = 128; off > 0; off >>= 1) {
            if (tid < off) red[tid] += red[tid + off];
            __syncthreads();
        }
        float dot = red[0];
        const float* b = cb + L * NF;
        for (int j = tid; j < NF; j += 256)
            xi[j] = fmaf(x0[j], dot, b[j] + xi[j]);
        __syncthreads();
    }

    float s = 0.f;
    for (int j = tid; j < NF; j += 256) s += xi[j] * wout[j];
    red[tid] = s;
    __syncthreads();
    #pragma unroll
    for (int off = 128; off > 0; off >>= 1) {
        if (tid < off) red[tid] += red[tid + off];
        __syncthreads();
    }
    if (tid == 0) g_cross_partial[row] = red[0];
}

// ---------------------------------------------------------------------------
// 4. Tensor-core GEMM: C = A(fp32->tf32) @ (Bhi + Blo) + bias
//    mma.sync.m16n8k8 tf32. BM=128, BN=128, BK=16, 256 threads (8 warps).
//    Warp tile 64x32 (4x4 m16n8 frags). B split hi/lo for fp32-class accuracy.
//    Requires M%128==0, N%128==0, K%16==0.
// ---------------------------------------------------------------------------
__device__ __forceinline__ uint32_t f2tf32(float v) {
    uint32_t r;
    asm("cvt.rna.tf32.f32 %0, %1;" : "=r"(r) : "f"(v));
    return r;
}

#define MMA_TF32(d0,d1,d2,d3,a0,a1,a2,a3,b0,b1)                         \
    asm volatile("mma.sync.aligned.m16n8k8.row.col.f32.tf32.tf32.f32 "   \
        "{%0,%1,%2,%3}, {%4,%5,%6,%7}, {%8,%9}, {%0,%1,%2,%3};\n"        \
        : "+f"(d0), "+f"(d1), "+f"(d2), "+f"(d3)                         \
        : "r"(a0), "r"(a1), "r"(a2), "r"(a3), "r"(b0), "r"(b1))

#define SMS 136   // smem row stride (128 + 8 pad) -> conflict-free frag loads

__global__ __launch_bounds__(256, 1)
void tgemm_bias(int M, int N, int K,
                const float* __restrict__ A, int lda,
                const float* __restrict__ Bm, int ldb,
                const float* __restrict__ bias,
                float* __restrict__ C, int ldc)
{
    __shared__ float As[16 * SMS];
    __shared__ float Bh[16 * SMS];
    __shared__ float Bl[16 * SMS];

    const int tid  = threadIdx.x;
    const int lane = tid & 31;
    const int warp = tid >> 5;
    const int wm = warp >> 2;          // 0..1
    const int wn = warp & 3;           // 0..3
    const int g  = lane >> 2;          // 0..7
    const int tg = lane & 3;           // 0..3

    // global load mapping
    const int arow = tid >> 1;                 // 0..127
    const int acol = (tid & 1) * 8;            // 0 or 8
    const int brow = tid >> 4;                 // 0..15
    const int bcol = (tid & 15) * 8;           // 0..120

    const float* Abase = A + ((size_t)blockIdx.y * 128 + arow) * lda + acol;
    const float* Bbase = Bm + (size_t)blockIdx.x * 128 + bcol;

    float acc[4][4][4];
    #pragma unroll
    for (int i = 0; i < 4; i++)
        #pragma unroll
        for (int j = 0; j < 4; j++)
            #pragma unroll
            for (int c = 0; c < 4; c++) acc[i][j][c] = 0.f;

    float4 ap0 = *(const float4*)(Abase);
    float4 ap1 = *(const float4*)(Abase + 4);
    float4 bp0 = *(const float4*)(Bbase + (size_t)brow * ldb);
    float4 bp1 = *(const float4*)(Bbase + (size_t)brow * ldb + 4);

    for (int k0 = 0; k0 < K; k0 += 16) {
        __syncthreads();   // previous compute done before overwriting smem

        // ---- store A tile (transposed to [k][m]) as rna-tf32 ----
        {
            float av[8] = {ap0.x, ap0.y, ap0.z, ap0.w, ap1.x, ap1.y, ap1.z, ap1.w};
            #pragma unroll
            for (int j = 0; j < 8; j++)
                As[(acol + j) * SMS + arow] = __uint_as_float(f2tf32(av[j]));
        }
        // ---- store B tile hi/lo ----
        {
            float bv[8] = {bp0.x, bp0.y, bp0.z, bp0.w, bp1.x, bp1.y, bp1.z, bp1.w};
            #pragma unroll
            for (int j = 0; j < 8; j++) {
                uint32_t hi = f2tf32(bv[j]);
                float hif = __uint_as_float(hi);
                uint32_t lo = f2tf32(bv[j] - hif);
                Bh[brow * SMS + bcol + j] = hif;
                Bl[brow * SMS + bcol + j] = __uint_as_float(lo);
            }
        }

        // ---- prefetch next tile ----
        if (k0 + 16 < K) {
            const float* an = Abase + (k0 + 16);
            ap0 = *(const float4*)(an);
            ap1 = *(const float4*)(an + 4);
            const float* bn = Bbase + (size_t)(k0 + 16 + brow) * ldb;
            bp0 = *(const float4*)(bn);
            bp1 = *(const float4*)(bn + 4);
        }
        __syncthreads();

        // ---- compute: 2 k-steps of 8 ----
        #pragma unroll
        for (int ks = 0; ks < 2; ks++) {
            const int kb = ks * 8;
            uint32_t af[4][4];
            #pragma unroll
            for (int mt = 0; mt < 4; mt++) {
                int m = wm * 64 + mt * 16 + g;
                af[mt][0] = __float_as_uint(As[(kb + tg    ) * SMS + m    ]);
                af[mt][1] = __float_as_uint(As[(kb + tg    ) * SMS + m + 8]);
                af[mt][2] = __float_as_uint(As[(kb + tg + 4) * SMS + m    ]);
                af[mt][3] = __float_as_uint(As[(kb + tg + 4) * SMS + m + 8]);
            }
            uint32_t bfh[4][2], bfl[4][2];
            #pragma unroll
            for (int nt = 0; nt < 4; nt++) {
                int n = wn * 32 + nt * 8 + g;
                bfh[nt][0] = __float_as_uint(Bh[(kb + tg    ) * SMS + n]);
                bfh[nt][1] = __float_as_uint(Bh[(kb + tg + 4) * SMS + n]);
                bfl[nt][0] = __float_as_uint(Bl[(kb + tg    ) * SMS + n]);
                bfl[nt][1] = __float_as_uint(Bl[(kb + tg + 4) * SMS + n]);
            }
            #pragma unroll
            for (int mt = 0; mt < 4; mt++)
                #pragma unroll
                for (int nt = 0; nt < 4; nt++) {
                    MMA_TF32(acc[mt][nt][0], acc[mt][nt][1], acc[mt][nt][2], acc[mt][nt][3],
                             af[mt][0], af[mt][1], af[mt][2], af[mt][3],
                             bfh[nt][0], bfh[nt][1]);
                    MMA_TF32(acc[mt][nt][0], acc[mt][nt][1], acc[mt][nt][2], acc[mt][nt][3],
                             af[mt][0], af[mt][1], af[mt][2], af[mt][3],
                             bfl[nt][0], bfl[nt][1]);
                }
        }
    }

    // ---- epilogue: + bias, store ----
    #pragma unroll
    for (int mt = 0; mt < 4; mt++) {
        int row0 = blockIdx.y * 128 + wm * 64 + mt * 16 + g;
        #pragma unroll
        for (int nt = 0; nt < 4; nt++) {
            int col = blockIdx.x * 128 + wn * 32 + nt * 8 + tg * 2;
            float b0 = bias[col], b1 = bias[col + 1];
            float2 v0 = make_float2(acc[mt][nt][0] + b0, acc[mt][nt][1] + b1);
            float2 v1 = make_float2(acc[mt][nt][2] + b0, acc[mt][nt][3] + b1);
            *(float2*)(C + (size_t)row0 * ldc + col)       = v0;
            *(float2*)(C + (size_t)(row0 + 8) * ldc + col) = v1;
        }
    }
}

// ---------------------------------------------------------------------------
// 5. Pad W1 (1725 x 1024) into g_w1p (1728 x 1024), zero tail rows
// ---------------------------------------------------------------------------
__global__ void pad_w1(const float* __restrict__ W1)
{
    long i = (long)blockIdx.x * blockDim.x + threadIdx.x;
    long total = (long)LDH * N1;
    if (i >= total) return;
    int k = (int)(i / N1);
    g_w1p[i] = (k < NF) ? W1[i] : 0.0f;
}

// ---------------------------------------------------------------------------
// 6. Final: logits = cross_partial + a3 . Wout[1725:1981]; sigmoid
// ---------------------------------------------------------------------------
__global__ void final_kernel(const float* __restrict__ wout_tail,
                             float* __restrict__ out)
{
    int row  = blockIdx.x * 8 + (threadIdx.x >> 5);
    int lane = threadIdx.x & 31;
    const float* r = g_z3 + (size_t)row * N3;
    float s = 0.f;
    #pragma unroll
    for (int j = lane; j < N3; j += 32) s += r[j] * wout_tail[j];
    #pragma unroll
    for (int off = 16; off > 0; off >>= 1)
        s += __shfl_down_sync(0xffffffffu, s, off);
    if (lane == 0) {
        float z = s + g_cross_partial[row];
        out[row] = 1.0f / (1.0f + expf(-z));
    }
}

// ---------------------------------------------------------------------------
// Launcher
// ---------------------------------------------------------------------------
extern "C" void kernel_launch(void* const* d_in, const int* in_sizes, int n_in,
                              void* d_out, int out_size)
{
    const int*   sparse  = (const int*)  d_in[0];
    const float* dense   = (const float*)d_in[1];
    const float* emb_a   = (const float*)d_in[2];
    const float* emb_b   = (const float*)d_in[3];
    const float* emb_c   = (const float*)d_in[4];
    const float* cross_w = (const float*)d_in[5];
    const float* cross_b = (const float*)d_in[6];
    const float* W1      = (const float*)d_in[7];
    const float* b1      = (const float*)d_in[8];
    const float* W2      = (const float*)d_in[9];
    const float* b2      = (const float*)d_in[10];
    const float* W3      = (const float*)d_in[11];
    const float* b3      = (const float*)d_in[12];
    const float* Wout    = (const float*)d_in[13];
    float* out = (float*)d_out;

    float *ph, *pw1p, *pz1, *pz2, *pz3;
    cudaGetSymbolAddress((void**)&ph,   g_h);
    cudaGetSymbolAddress((void**)&pw1p, g_w1p);
    cudaGetSymbolAddress((void**)&pz1,  g_z1);
    cudaGetSymbolAddress((void**)&pz2,  g_z2);
    cudaGetSymbolAddress((void**)&pz3,  g_z3);

    // ---- pad W1 ----
    {
        long total = (long)LDH * N1;
        pad_w1<<<(int)((total + 255) / 256), 256>>>(W1);
    }

    // ---- gather ----
    gather_kernel<<<B, 256>>>(sparse, dense, emb_a, emb_b, emb_c);

    // ---- BN(h) ----
    {
        dim3 g((LDH + 127) / 128, NCHUNK);
        colstats_partial<<<g, 128>>>(ph, LDH, LDH);
        colstats_final<<<(LDH + 127) / 128, 128>>>(LDH);
        long t4 = (long)B * (LDH / 4);
        bn_apply_v4<<<(int)((t4 + 255) / 256), 256>>>((float4*)ph, LDH / 4, t4, 0);
    }

    // ---- cross network (fused with Wout head) ----
    cross_kernel<<<B, 256>>>(cross_w, cross_b, Wout);

    // ---- layer 1: z1 = h @ W1p + b1; BN; relu ----
    {
        dim3 grid(N1 / 128, B / 128);
        tgemm_bias<<<grid, 256>>>(B, N1, LDH, ph, LDH, pw1p, N1, b1, pz1, N1);
        dim3 g((N1 + 127) / 128, NCHUNK);
        colstats_partial<<<g, 128>>>(pz1, N1, N1);
        colstats_final<<<(N1 + 127) / 128, 128>>>(N1);
        long t4 = (long)B * (N1 / 4);
        bn_apply_v4<<<(int)((t4 + 255) / 256), 256>>>((float4*)pz1, N1 / 4, t4, 1);
    }

    // ---- layer 2 ----
    {
        dim3 grid(N2 / 128, B / 128);
        tgemm_bias<<<grid, 256>>>(B, N2, N1, pz1, N1, W2, N2, b2, pz2, N2);
        dim3 g((N2 + 127) / 128, NCHUNK);
        colstats_partial<<<g, 128>>>(pz2, N2, N2);
        colstats_final<<<(N2 + 127) / 128, 128>>>(N2);
        long t4 = (long)B * (N2 / 4);
        bn_apply_v4<<<(int)((t4 + 255) / 256), 256>>>((float4*)pz2, N2 / 4, t4, 1);
    }

    // ---- layer 3 ----
    {
        dim3 grid(N3 / 128, B / 128);
        tgemm_bias<<<grid, 256>>>(B, N3, N2, pz2, N2, W3, N3, b3, pz3, N3);
        dim3 g((N3 + 127) / 128, NCHUNK);
        colstats_partial<<<g, 128>>>(pz3, N3, N3);
        colstats_final<<<(N3 + 127) / 128, 128>>>(N3);
        long t4 = (long)B * (N3 / 4);
        bn_apply_v4<<<(int)((t4 + 255) / 256), 256>>>((float4*)pz3, N3 / 4, t4, 1);
    }

    // ---- final head ----
    final_kernel<<<B / 8, 256>>>(Wout + NF, out);
}